// round 4
// baseline (speedup 1.0000x reference)
#include <cuda_runtime.h>
#include <math.h>

#define N_S 1024
#define XD  128
#define HID 256

typedef unsigned long long u64;

__device__ __align__(16) float g_xpT[HID * N_S];   // xp transposed: [h][j]
__device__ __align__(16) float g_ypb[N_S * HID];   // yp + b1:       [i][h]
__device__ float g_t0[N_S];
__device__ float g_part[N_S * 2];                  // partial exp-sums [i][jhalf]

// ---------------------------------------------------------------------------
// packed f32x2 helpers (sm_103a)
// ---------------------------------------------------------------------------
__device__ __forceinline__ u64 f2add(u64 a, u64 b) {
    u64 r; asm("add.rn.f32x2 %0,%1,%2;" : "=l"(r) : "l"(a), "l"(b)); return r;
}
__device__ __forceinline__ u64 f2fma(u64 a, u64 b, u64 c) {
    u64 r; asm("fma.rn.f32x2 %0,%1,%2,%3;" : "=l"(r) : "l"(a), "l"(b), "l"(c));
    return r;
}
__device__ __forceinline__ u64 f2relu(u64 a) {
    unsigned lo, hi;
    asm("mov.b64 {%0,%1},%2;" : "=r"(lo), "=r"(hi) : "l"(a));
    float flo = fmaxf(__uint_as_float(lo), 0.f);
    float fhi = fmaxf(__uint_as_float(hi), 0.f);
    u64 r;
    asm("mov.b64 %0,{%1,%2};" : "=l"(r)
        : "r"(__float_as_uint(flo)), "r"(__float_as_uint(fhi)));
    return r;
}
__device__ __forceinline__ u64 dupf(float v) {
    unsigned u = __float_as_uint(v);
    u64 r; asm("mov.b64 %0,{%1,%1};" : "=l"(r) : "r"(u)); return r;
}

// ---------------------------------------------------------------------------
// Projection: xp = x @ W1[:128] (transposed store), ypb = y @ W1[128:] + b1
// grid (64, 2), block 256. 16 rows/CTA (4x less W traffic).
// Thread = (row-group rg, h-pair ht). f32x2 FFMA2 throughout.
// ---------------------------------------------------------------------------
__global__ void __launch_bounds__(256) proj_kernel(const float* __restrict__ x,
                                                   const float* __restrict__ y,
                                                   const float* __restrict__ W1,
                                                   const float* __restrict__ b1) {
    __shared__ __align__(16) u64 xd[16][XD];   // x values as dup pairs, 16KB
    const int t  = threadIdx.x;
    const int rg = t >> 7;                     // row group 0/1 (8 rows each)
    const int ht = t & 127;                    // h-pair index: h = 2ht, 2ht+1
    const int rb = blockIdx.x * 16;
    const float* src = (blockIdx.y == 0) ? x : y;

    for (int idx = t; idx < 16 * XD; idx += 256) {
        xd[idx >> 7][idx & 127] = dupf(src[(rb + (idx >> 7)) * XD + (idx & 127)]);
    }
    __syncthreads();

    const u64* Wb64 = reinterpret_cast<const u64*>(
        W1 + (blockIdx.y == 0 ? 0 : XD * HID));   // [k][128 h-pairs]

    u64 acc[8];
    #pragma unroll
    for (int r = 0; r < 8; r++) acc[r] = 0ull;

    u64 ring[8];
    #pragma unroll
    for (int p = 0; p < 8; p++) ring[p] = Wb64[p * 128 + ht];

    const int r0 = rg * 8;
    for (int kb = 0; kb < XD; kb += 8) {
        #pragma unroll
        for (int p = 0; p < 8; p++) {
            const u64 w = ring[p];
            if (kb < XD - 8) ring[p] = Wb64[(kb + 8 + p) * 128 + ht];
            #pragma unroll
            for (int r = 0; r < 8; r++) {
                acc[r] = f2fma(xd[r0 + r][kb + p], w, acc[r]);
            }
        }
    }

    if (blockIdx.y == 0) {
        #pragma unroll
        for (int r = 0; r < 8; r++) {
            const int row = rb + r0 + r;
            unsigned lo, hi;
            asm("mov.b64 {%0,%1},%2;" : "=r"(lo), "=r"(hi) : "l"(acc[r]));
            g_xpT[(2 * ht)     * N_S + row] = __uint_as_float(lo);
            g_xpT[(2 * ht + 1) * N_S + row] = __uint_as_float(hi);
        }
    } else {
        const u64 bb = reinterpret_cast<const u64*>(b1)[ht];
        #pragma unroll
        for (int r = 0; r < 8; r++) {
            const int row = rb + r0 + r;
            *reinterpret_cast<u64*>(&g_ypb[row * HID + 2 * ht]) =
                f2add(acc[r], bb);
        }
    }
}

// ---------------------------------------------------------------------------
// Main: T1[i,j] = sum_h relu(ypb[i,h] + xp[j,h]) * W2[h]  (+b2 in epilogue)
// grid 148 = 74 i-blocks (62x14 rows + 12x13) x 2 j-halves (512 j each).
// block 512: group g=t>>8 handles 7 rows; thread owns one j-pair (f32x2).
// Writes partial exp-sums to g_part; finalize merges the two j-halves.
// ---------------------------------------------------------------------------
__global__ void __launch_bounds__(512) main_kernel(const float* __restrict__ W2,
                                                   const float* __restrict__ b2) {
    __shared__ __align__(16) u64 s_y[2][HID][8];  // [g][h][slot] dup pairs, 32KB
    __shared__ __align__(16) u64 s_w[HID];        // dup pairs
    __shared__ float red[112];                    // [row14][8 warps]

    const int t   = threadIdx.x;
    const int ibk = blockIdx.x >> 1;             // i-block 0..73
    const int jh  = blockIdx.x & 1;              // j-half
    const int nrows = (ibk < 62) ? 14 : 13;
    const int ib    = (ibk < 62) ? ibk * 14 : 868 + (ibk - 62) * 13;

    const int g  = t >> 8;                       // row group 0/1
    const int tt = t & 255;
    const int jp = (jh << 8) + tt;               // j-pair index 0..511
    const int j0 = 2 * jp;

    // stage ypb dup pairs: 16 slots (2 groups x 8; slot 7 of each = pad/dup)
    for (int idx = t; idx < HID * 16; idx += 512) {
        const int h  = idx & 255;
        const int sl = idx >> 8;                  // 0..15
        const int sg = sl >> 3, si = sl & 7;
        int row = sg * 7 + (si < 7 ? si : 6);
        if (row > nrows - 1) row = nrows - 1;
        s_y[sg][h][si] = dupf(g_ypb[(ib + row) * HID + h]);
    }
    if (t < HID) s_w[t] = dupf(W2[t]);
    __syncthreads();

    u64 acc[7];
    #pragma unroll
    for (int i = 0; i < 7; i++) acc[i] = 0ull;

    const u64* xp = reinterpret_cast<const u64*>(g_xpT) + jp;  // + h*512

    u64 xb[8];
    #pragma unroll
    for (int p = 0; p < 8; p++) xb[p] = xp[p * 512];

    for (int hb = 0; hb < HID; hb += 8) {
        #pragma unroll
        for (int p = 0; p < 8; p++) {
            const int h = hb + p;
            const u64 xx = xb[p];
            if (hb < HID - 8) xb[p] = xp[(h + 8) * 512];
            const u64 ww = s_w[h];
            const u64* yrow = s_y[g][h];
            const ulonglong2 ya = *reinterpret_cast<const ulonglong2*>(&yrow[0]);
            const ulonglong2 yc = *reinterpret_cast<const ulonglong2*>(&yrow[2]);
            const ulonglong2 ye = *reinterpret_cast<const ulonglong2*>(&yrow[4]);
            const u64 y6 = yrow[6];
            acc[0] = f2fma(f2relu(f2add(ya.x, xx)), ww, acc[0]);
            acc[1] = f2fma(f2relu(f2add(ya.y, xx)), ww, acc[1]);
            acc[2] = f2fma(f2relu(f2add(yc.x, xx)), ww, acc[2]);
            acc[3] = f2fma(f2relu(f2add(yc.y, xx)), ww, acc[3]);
            acc[4] = f2fma(f2relu(f2add(ye.x, xx)), ww, acc[4]);
            acc[5] = f2fma(f2relu(f2add(ye.y, xx)), ww, acc[5]);
            acc[6] = f2fma(f2relu(f2add(y6,   xx)), ww, acc[6]);
        }
    }

    // Epilogue: per-row exp-sums over this CTA's 512 j; one barrier.
    const float b2v = b2[0];
    const int lane = t & 31;
    const int wrp  = (t >> 5) & 7;               // warp index within group

    #pragma unroll
    for (int i = 0; i < 7; i++) {
        const int rloc = g * 7 + i;              // 0..13
        const int ig   = ib + rloc;
        const bool valid = (g == 0) || (i < nrows - 7);
        unsigned lo, hi;
        asm("mov.b64 {%0,%1},%2;" : "=r"(lo), "=r"(hi) : "l"(acc[i]));
        const float v0 = __uint_as_float(lo) + b2v;
        const float v1 = __uint_as_float(hi) + b2v;
        if (valid) {
            if (j0     == ig) g_t0[ig] = v0;     // diagonal T0
            if (j0 + 1 == ig) g_t0[ig] = v1;
        }
        float s = valid ? (__expf(v0) + __expf(v1)) : 0.f;
        #pragma unroll
        for (int o = 16; o > 0; o >>= 1) s += __shfl_xor_sync(0xffffffffu, s, o);
        if (lane == 0) red[rloc * 8 + wrp] = s;
    }
    __syncthreads();

    if (t < 112) {
        const int row = t >> 3;                  // 0..13
        float v = red[t];
        #pragma unroll
        for (int o = 4; o > 0; o >>= 1) v += __shfl_xor_sync(0xffffffffu, v, o);
        if ((t & 7) == 0 && row < nrows) {
            g_part[(ib + row) * 2 + jh] = v;
        }
    }
}

// ---------------------------------------------------------------------------
// Finalize: lb = mean(T0) - (mean(log(part0+part1)) - log(N))
// ---------------------------------------------------------------------------
__global__ void __launch_bounds__(256) finalize_kernel(float* __restrict__ out) {
    __shared__ float r1[256], r2[256];
    const int t = threadIdx.x;
    float a = 0.f, b = 0.f;
    #pragma unroll
    for (int p = 0; p < 4; p++) {
        const int i = t + 256 * p;
        a += g_t0[i];
        b += logf(g_part[2 * i] + g_part[2 * i + 1]);
    }
    r1[t] = a; r2[t] = b;
    __syncthreads();
    for (int off = 128; off > 0; off >>= 1) {
        if (t < off) { r1[t] += r1[t + off]; r2[t] += r2[t + off]; }
        __syncthreads();
    }
    if (t == 0) {
        out[0] = r1[0] / (float)N_S - (r2[0] / (float)N_S - logf((float)N_S));
    }
}

// ---------------------------------------------------------------------------
extern "C" void kernel_launch(void* const* d_in, const int* in_sizes, int n_in,
                              void* d_out, int out_size) {
    const float* x  = (const float*)d_in[0];
    const float* y  = (const float*)d_in[1];
    const float* W1 = (const float*)d_in[2];
    const float* b1 = (const float*)d_in[3];
    const float* W2 = (const float*)d_in[4];
    const float* b2 = (const float*)d_in[5];

    proj_kernel<<<dim3(64, 2), 256>>>(x, y, W1, b1);
    main_kernel<<<148, 512>>>(W2, b2);
    finalize_kernel<<<1, 256>>>((float*)d_out);
}